// round 17
// baseline (speedup 1.0000x reference)
#include <cuda_runtime.h>
#include <cuda_fp16.h>
#include <math.h>

// Problem shape (fixed): B=2, H=12, S=1024, D=64
#define BB 2
#define HH 12
#define SS 1024
#define DD 64
#define KP 102            // k_precise = int(1024 * 0.1)
#define NROWS (BB*HH*SS)  // 24576

__device__ unsigned long long g_kbits[NROWS];
__device__ __half2 g_kh[NROWS * DD / 2];   // fp16 copy of K (3.1 MB)
__device__ __half2 g_vh[NROWS * DD / 2];   // fp16 copy of V (3.1 MB)

// ---------------------------------------------------------------------------
// Prologue: one warp per row. Sign bits from fp32 K (selection bit-identical
// to reference) + fp16 conversion of K and V rows in the same pass.
// ---------------------------------------------------------------------------
__global__ void prologue_kernel(const float* __restrict__ k,
                                const float* __restrict__ v) {
    int warp = (blockIdx.x * blockDim.x + threadIdx.x) >> 5;
    int lane = threadIdx.x & 31;
    if (warp >= NROWS) return;

    const float* kr = k + (size_t)warp * DD;
    unsigned lo = __ballot_sync(0xffffffffu, kr[lane]      > 0.0f);
    unsigned hi = __ballot_sync(0xffffffffu, kr[lane + 32] > 0.0f);
    if (lane == 0)
        g_kbits[warp] = (unsigned long long)lo | ((unsigned long long)hi << 32);

    // fp16 copies (K row re-read hits L1; V read once)
    float2 kc = ((const float2*)kr)[lane];
    g_kh[(size_t)warp * 32 + lane] = __float22half2_rn(kc);
    float2 vc = ((const float2*)(v + (size_t)warp * DD))[lane];
    g_vh[(size_t)warp * 32 + lane] = __float22half2_rn(vc);
}

// ---------------------------------------------------------------------------
// Kernel 2: one CTA (128 threads = 4 warps) per query.
// ---------------------------------------------------------------------------
__global__ __launch_bounds__(128, 16)
void attn_kernel(const float* __restrict__ q,
                 const float* __restrict__ mask,
                 float* __restrict__ out) {
    __shared__ float4 s_acc4[8][16];        // v partial sums (16B aligned)
    __shared__ float2 s_pi[KP + 2];         // .x prob, .y idx bits
    __shared__ int    s_hist[4 * 66];       // per-warp histograms
    __shared__ int    s_histm[65];          // merged
    __shared__ int    s_wcnt[32];           // packed lt|eq counts per (it,warp)
    __shared__ unsigned s_lb[32];           // lt ballots per (it,warp)
    __shared__ unsigned s_eb[32];           // eq ballots per (it,warp)
    __shared__ unsigned char s_popc[SS];    // popcounts
    __shared__ int    s_idx[KP + 2];        // selected key indices (ascending)
    __shared__ float  s_red[4];
    __shared__ int    s_ps[2];              // pstar, r
    __shared__ unsigned long long s_qbit;

    const int qid  = blockIdx.x;            // 0..B*H*S-1
    const int bh   = qid >> 10;
    const int b    = bh / HH;
    const int tid  = threadIdx.x;
    const int lane = tid & 31;
    const int w    = tid >> 5;
    const unsigned full = 0xffffffffu;
    const unsigned ltm  = (1u << lane) - 1u;

    // ---- query sign bits computed in-block (warp 0) ----
    const float* qrow = q + (size_t)qid * DD;
    if (w == 0) {
        unsigned lo = __ballot_sync(full, qrow[lane]      > 0.0f);
        unsigned hi = __ballot_sync(full, qrow[lane + 32] > 0.0f);
        if (lane == 0)
            s_qbit = (unsigned long long)lo | ((unsigned long long)hi << 32);
    }
    for (int e = lane; e < 65; e += 32) s_hist[w * 66 + e] = 0;
    __syncthreads();
    const unsigned long long qbit = s_qbit;

    // ---- Phase A: popcounts -> shared + per-warp histograms ----
    const unsigned long long* kb = g_kbits + (size_t)bh * SS;
    #pragma unroll
    for (int it = 0; it < 8; ++it) {
        const int p = __popcll(qbit ^ kb[it * 128 + tid]);
        s_popc[it * 128 + tid] = (unsigned char)p;
        unsigned grp = __match_any_sync(full, p);
        if ((__ffs(grp) - 1) == lane)
            atomicAdd(&s_hist[w * 66 + p], __popc(grp));
    }
    __syncthreads();
    if (tid < 65)
        s_histm[tid] = s_hist[tid] + s_hist[66 + tid]
                     + s_hist[132 + tid] + s_hist[198 + tid];
    __syncthreads();

    // ---- threshold via warp-0 prefix scan over bins ----
    if (w == 0) {
        int h = s_histm[lane];              // bins 0..31
        int c = h;
        #pragma unroll
        for (int off = 1; off < 32; off <<= 1) {
            int t = __shfl_up_sync(full, c, off);
            if (lane >= off) c += t;
        }
        int tot_lo = __shfl_sync(full, c, 31);
        int pstar, r;
        if (tot_lo >= KP) {
            unsigned bb = __ballot_sync(full, c >= KP);
            int l = __ffs(bb) - 1;
            pstar = l;
            r = KP - __shfl_sync(full, c - h, l);
        } else {
            int h2 = s_histm[32 + lane];    // bins 32..63
            int c2 = h2;
            #pragma unroll
            for (int off = 1; off < 32; off <<= 1) {
                int t = __shfl_up_sync(full, c2, off);
                if (lane >= off) c2 += t;
            }
            c2 += tot_lo;
            unsigned bb = __ballot_sync(full, c2 >= KP);
            if (bb) {
                int l = __ffs(bb) - 1;
                pstar = 32 + l;
                r = KP - __shfl_sync(full, c2 - h2, l);
            } else {
                pstar = 64;
                r = KP - __shfl_sync(full, c2, 31);
            }
        }
        if (lane == 0) { s_ps[0] = pstar; s_ps[1] = r; }
    }
    __syncthreads();
    const int pstar = s_ps[0];
    const int r     = s_ps[1];

    // ---- Phase B: deterministic ordered compaction (no atomics) ----
    #pragma unroll
    for (int it = 0; it < 8; ++it) {
        const int p = s_popc[it * 128 + tid];
        unsigned lb = __ballot_sync(full, p <  pstar);
        unsigned eb = __ballot_sync(full, p == pstar);
        if (lane == 0) {
            s_wcnt[it * 4 + w] = __popc(lb) | (__popc(eb) << 16);
            s_lb[it * 4 + w] = lb;
            s_eb[it * 4 + w] = eb;
        }
    }
    __syncthreads();
    {
        int vcnt = s_wcnt[lane];
        int c = vcnt;
        #pragma unroll
        for (int off = 1; off < 32; off <<= 1) {
            int t = __shfl_up_sync(full, c, off);
            if (lane >= off) c += t;
        }
        int excl = c - vcnt;
        int nlt  = __shfl_sync(full, c, 31) & 0xffff;   // == KP - r
        #pragma unroll
        for (int it = 0; it < 8; ++it) {
            const unsigned lb = s_lb[it * 4 + w];
            const unsigned eb = s_eb[it * 4 + w];
            int pref = __shfl_sync(full, excl, it * 4 + w);
            int i = it * 128 + tid;
            if ((lb >> lane) & 1u) {
                s_idx[(pref & 0xffff) + __popc(lb & ltm)] = i;
            } else if ((eb >> lane) & 1u) {
                int rk = (pref >> 16) + __popc(eb & ltm);
                if (rk < r) s_idx[nlt + rk] = i;
            }
        }
    }
    __syncthreads();

    // ---- Phase C1: precise scores from fp16 K; 1 LDG.128 per key ----
    const __half2* kbase = g_kh + (size_t)bh * SS * 32;
    const float* mrow    = mask + (size_t)b * SS;
    {
        const int grp4 = lane >> 3;
        const int l8   = lane & 7;
        const float4* qr4 = (const float4*)qrow;
        const float4 qa = qr4[l8 * 2];       // dims l8*8 .. l8*8+3
        const float4 qb = qr4[l8 * 2 + 1];   // dims l8*8+4 .. l8*8+7
        #pragma unroll 2
        for (int i = 0; i < 7; ++i) {
            const int j = i * 16 + w * 4 + grp4;
            const bool valid = (j < KP);
            const int idx = s_idx[valid ? j : 0];
            const uint4 raw =
                *(const uint4*)(kbase + (size_t)idx * 32 + l8 * 4);
            const float2 f0 = __half22float2(*(const __half2*)&raw.x);
            const float2 f1 = __half22float2(*(const __half2*)&raw.y);
            const float2 f2 = __half22float2(*(const __half2*)&raw.z);
            const float2 f3 = __half22float2(*(const __half2*)&raw.w);
            float part = qa.x * f0.x + qa.y * f0.y + qa.z * f1.x + qa.w * f1.y
                       + qb.x * f2.x + qb.y * f2.y + qb.z * f3.x + qb.w * f3.y;
            part += __shfl_xor_sync(full, part, 4);
            part += __shfl_xor_sync(full, part, 2);
            part += __shfl_xor_sync(full, part, 1);
            if (valid && l8 == 0)
                s_pi[j].x = part * 0.125f + __ldg(&mrow[idx]);
        }
    }
    __syncthreads();

    // ---- softmax (normalized probs written packed with idx) ----
    {
        const float sc = (tid < KP) ? s_pi[tid].x : -INFINITY;
        float mx = sc;
        #pragma unroll
        for (int off = 16; off; off >>= 1)
            mx = fmaxf(mx, __shfl_xor_sync(full, mx, off));
        if (lane == 0) s_red[w] = mx;
        __syncthreads();
        const float m = fmaxf(fmaxf(s_red[0], s_red[1]),
                              fmaxf(s_red[2], s_red[3]));
        __syncthreads();
        const float e = (tid < KP) ? __expf(sc - m) : 0.0f;
        float sm = e;
        #pragma unroll
        for (int off = 16; off; off >>= 1)
            sm += __shfl_xor_sync(full, sm, off);
        if (lane == 0) s_red[w] = sm;
        __syncthreads();
        const float inv = 1.0f / (s_red[0] + s_red[1] + s_red[2] + s_red[3]);
        if (tid < KP)
            s_pi[tid] = make_float2(e * inv, __int_as_float(s_idx[tid]));
    }
    __syncthreads();

    // ---- Phase C2: prob-weighted V from fp16 V; 1 line per key ----
    const __half2* vbase = g_vh + (size_t)bh * SS * 32;
    {
        const int g   = tid >> 4;           // 0..7
        const int l16 = tid & 15;
        const int lo  = g * 13;
        const int hi  = (lo + 13 < KP) ? lo + 13 : KP;
        float4 acc = make_float4(0.f, 0.f, 0.f, 0.f);
        #pragma unroll 2
        for (int j = lo; j < hi; ++j) {
            const float2 pi = s_pi[j];
            const int idx = __float_as_int(pi.y);
            const uint2 raw =
                *(const uint2*)(vbase + (size_t)idx * 32 + l16 * 2);
            const float2 v0 = __half22float2(*(const __half2*)&raw.x);
            const float2 v1 = __half22float2(*(const __half2*)&raw.y);
            acc.x += pi.x * v0.x;
            acc.y += pi.x * v0.y;
            acc.z += pi.x * v1.x;
            acc.w += pi.x * v1.y;
        }
        s_acc4[g][l16] = acc;
    }
    __syncthreads();
    if (tid < DD) {
        const float* col = (const float*)&s_acc4[0][0] + tid;
        float s = 0.0f;
        #pragma unroll
        for (int g = 0; g < 8; ++g) s += col[g * DD];
        out[(size_t)qid * DD + tid] = s;
    }
}

// ---------------------------------------------------------------------------
extern "C" void kernel_launch(void* const* d_in, const int* in_sizes, int n_in,
                              void* d_out, int out_size) {
    const float* q    = (const float*)d_in[0];
    const float* k    = (const float*)d_in[1];
    const float* v    = (const float*)d_in[2];
    const float* mask = (const float*)d_in[3];
    float* out        = (float*)d_out;

    {
        int total_threads = NROWS * 32;
        int block = 256;
        int grid = (total_threads + block - 1) / block;
        prologue_kernel<<<grid, block>>>(k, v);
    }
    attn_kernel<<<NROWS, 128>>>(q, mask, out);
}